// round 7
// baseline (speedup 1.0000x reference)
#include <cuda_runtime.h>
#include <cuda_fp16.h>
#include <cstdint>
#include <cstddef>

// y[M,N] = x[M,K] @ W[N,K]^T * scale + bias   M=16384, N=4096, K=4096
// tcgen05 cta_group::2 (cluster 2): 256x256 tile per CTA pair, -33% L2 traffic.
// x fp32->fp16 scratch, w int32->fp16 (ints <127 exact), fp32 accumulate.

#define MM 16384
#define NN 4096
#define KK 4096

#define TILE_M 256             // per CTA pair (128 per CTA)
#define TILE_N 256
#define KC 64                  // halves per K-chunk = 128 bytes per row
#define STAGES 6
#define LEAD 4
#define NCHUNK (KK / KC)       // 64
#define GTHREADS 256

// HMMA fallback warp tiling (128x256 per CTA): 2 (M) x 4 (N) warps, each 64x64
#define WARP_M 64
#define WARP_N 64
#define MT 4
#define NT 8

__device__ __half g_xh[(size_t)MM * KK];   // 128 MB scratch
__device__ __half g_wh[(size_t)NN * KK];   // 32 MB scratch (L2 resident)

// tcgen05 path smem: per stage A(128rows)=16KB + B-half(128rows)=16KB
#define A_BYTES 16384
#define B_BYTES 16384
#define STAGE_BYTES (A_BYTES + B_BYTES)    // 32 KB
#define SMEM_TOTAL (1024 + STAGES * STAGE_BYTES)   // 197632
// header: [0] tmem ptr, ready[s] @ 16+8s (rank0), done[s] @ 80+8s (both ranks)

// HMMA fallback smem layout (4 stages x 48KB at offset 0, fits in SMEM_TOTAL)
#define HM_A_BYTES (128 * 128)
#define HM_B_BYTES (256 * 128)
#define HM_STAGE (HM_A_BYTES + HM_B_BYTES)

#define SWZ(o) ((o) ^ (((o) >> 3) & 0x70))

__device__ __forceinline__ uint32_t s2u(const void* p) {
    uint32_t a;
    asm("{ .reg .u64 t; cvta.to.shared.u64 t, %1; cvt.u32.u64 %0, t; }" : "=r"(a) : "l"(p));
    return a;
}

__device__ __forceinline__ void cp16(uint32_t dst, const void* src) {
    asm volatile("cp.async.cg.shared.global [%0], [%1], 16;" :: "r"(dst), "l"(src) : "memory");
}

// ---------------- HMMA helpers ----------------------------------------------
__device__ __forceinline__ void ldsm_x4(uint32_t* r, uint32_t addr) {
    asm volatile("ldmatrix.sync.aligned.m8n8.x4.shared.b16 {%0,%1,%2,%3}, [%4];"
                 : "=r"(r[0]), "=r"(r[1]), "=r"(r[2]), "=r"(r[3]) : "r"(addr));
}

__device__ __forceinline__ void mma16816(float* c, const uint32_t* a, const uint32_t* b) {
    asm volatile(
        "mma.sync.aligned.m16n8k16.row.col.f32.f16.f16.f32 "
        "{%0,%1,%2,%3}, {%4,%5,%6,%7}, {%8,%9}, {%0,%1,%2,%3};"
        : "+f"(c[0]), "+f"(c[1]), "+f"(c[2]), "+f"(c[3])
        : "r"(a[0]), "r"(a[1]), "r"(a[2]), "r"(a[3]), "r"(b[0]), "r"(b[1]));
}

// ---------------- mbarrier / tcgen05 helpers ---------------------------------
#define MBAR_INIT(a, c) \
    asm volatile("mbarrier.init.shared.b64 [%0], %1;" :: "r"(a), "r"(c) : "memory")

#define MBAR_WAIT(a, par) do {                                                  \
    uint32_t _m = (a), _p = (par);                                              \
    asm volatile(                                                               \
        "{\n\t.reg .pred P1;\n\t"                                               \
        "WL_%=:\n\t"                                                            \
        "mbarrier.try_wait.parity.acquire.cta.shared::cta.b64 P1, [%0], %1, 0x989680;\n\t" \
        "@P1 bra.uni WD_%=;\n\t"                                                \
        "bra.uni WL_%=;\n\t"                                                    \
        "WD_%=:\n\t}"                                                           \
        :: "r"(_m), "r"(_p) : "memory");                                        \
} while (0)

#define MBAR_WAIT_CLU(a, par) do {                                              \
    uint32_t _m = (a), _p = (par);                                              \
    asm volatile(                                                               \
        "{\n\t.reg .pred P1;\n\t"                                               \
        "WL_%=:\n\t"                                                            \
        "mbarrier.try_wait.parity.acquire.cluster.shared::cta.b64 P1, [%0], %1, 0x989680;\n\t" \
        "@P1 bra.uni WD_%=;\n\t"                                                \
        "bra.uni WL_%=;\n\t"                                                    \
        "WD_%=:\n\t}"                                                           \
        :: "r"(_m), "r"(_p) : "memory");                                        \
} while (0)

// arrive on rank0's mbarrier at the same smem offset (mapa handles self-rank)
#define MBAR_ARRIVE_RANK0(a)                                                    \
    asm volatile(                                                               \
        "{\n\t.reg .b32 ra;\n\t"                                                \
        "mapa.shared::cluster.u32 ra, %0, 0;\n\t"                               \
        "mbarrier.arrive.shared::cluster.b64 _, [ra];\n\t}"                     \
        :: "r"((uint32_t)(a)) : "memory")

#define TC_ALLOC_CG2(sa, n) \
    asm volatile("tcgen05.alloc.cta_group::2.sync.aligned.shared::cta.b32 [%0], %1;" \
                 :: "r"(sa), "r"((uint32_t)(n)) : "memory")
#define TC_DEALLOC_CG2(t, n) \
    asm volatile("tcgen05.dealloc.cta_group::2.sync.aligned.b32 %0, %1;" :: "r"(t), "r"((uint32_t)(n)))
#define TC_RELINQ_CG2() \
    asm volatile("tcgen05.relinquish_alloc_permit.cta_group::2.sync.aligned;")
#define TC_COMMIT_MC2(a) \
    asm volatile("tcgen05.commit.cta_group::2.mbarrier::arrive::one.shared::cluster.multicast::cluster.b64 [%0], %1;" \
                 :: "r"(a), "h"((uint16_t)0x3) : "memory")
#define TC_FENCE_AFTER()  asm volatile("tcgen05.fence::after_thread_sync;" ::: "memory")
#define TC_FENCE_BEFORE() asm volatile("tcgen05.fence::before_thread_sync;" ::: "memory")
#define TC_WAIT_LD()      asm volatile("tcgen05.wait::ld.sync.aligned;" ::: "memory")
#define FENCE_ASYNC()     asm volatile("fence.proxy.async.shared::cta;" ::: "memory")
#define CLUSTER_ARRIVE()  asm volatile("barrier.cluster.arrive.aligned;" ::: "memory")
#define CLUSTER_WAIT()    asm volatile("barrier.cluster.wait.aligned;" ::: "memory")

#define LDTM_X32(r, ta)                                                         \
    asm volatile(                                                               \
        "tcgen05.ld.sync.aligned.32x32b.x32.b32 "                               \
        "{%0, %1, %2, %3, %4, %5, %6, %7, "                                     \
        " %8, %9, %10, %11, %12, %13, %14, %15, "                               \
        " %16, %17, %18, %19, %20, %21, %22, %23, "                             \
        " %24, %25, %26, %27, %28, %29, %30, %31}, [%32];"                      \
        : "=r"((r)[0]),  "=r"((r)[1]),  "=r"((r)[2]),  "=r"((r)[3]),            \
          "=r"((r)[4]),  "=r"((r)[5]),  "=r"((r)[6]),  "=r"((r)[7]),            \
          "=r"((r)[8]),  "=r"((r)[9]),  "=r"((r)[10]), "=r"((r)[11]),           \
          "=r"((r)[12]), "=r"((r)[13]), "=r"((r)[14]), "=r"((r)[15]),           \
          "=r"((r)[16]), "=r"((r)[17]), "=r"((r)[18]), "=r"((r)[19]),           \
          "=r"((r)[20]), "=r"((r)[21]), "=r"((r)[22]), "=r"((r)[23]),           \
          "=r"((r)[24]), "=r"((r)[25]), "=r"((r)[26]), "=r"((r)[27]),           \
          "=r"((r)[28]), "=r"((r)[29]), "=r"((r)[30]), "=r"((r)[31])            \
        : "r"(ta))

// ---------------- conversion kernels ----------------------------------------
struct h4 { __half2 a, b; };

__global__ void cvt_x_kernel(const float4* __restrict__ x) {
    size_t i = (size_t)blockIdx.x * blockDim.x + threadIdx.x;
    float4 v = x[i];
    h4 o;
    o.a = __floats2half2_rn(v.x, v.y);
    o.b = __floats2half2_rn(v.z, v.w);
    reinterpret_cast<h4*>(g_xh)[i] = o;
}

__global__ void cvt_w_kernel(const int4* __restrict__ w) {
    size_t i = (size_t)blockIdx.x * blockDim.x + threadIdx.x;
    int4 v = w[i];
    h4 o;
    o.a = __halves2half2(__int2half_rn(v.x), __int2half_rn(v.y));
    o.b = __halves2half2(__int2half_rn(v.z), __int2half_rn(v.w));
    reinterpret_cast<h4*>(g_wh)[i] = o;
}

// ---------------- GEMM -------------------------------------------------------
// grid = (2, NN/256, MM/256); cluster (2,1,1) pairs blockIdx.x = rank
__global__ void __launch_bounds__(GTHREADS, 1) __cluster_dims__(2, 1, 1)
gemm_kernel(const float* __restrict__ scale, const float* __restrict__ bias,
            float* __restrict__ out) {
    extern __shared__ char smem[];
    const uint32_t sbase = s2u(smem);
    const int tid = threadIdx.x;
    const int wid = tid >> 5, lane = tid & 31;
    const int rank = blockIdx.x;               // cluster ctarank
    const int n0 = blockIdx.y * TILE_N;
    const int mp0 = blockIdx.z * TILE_M;       // pair M origin

#if defined(__CUDA_ARCH__) && defined(__CUDA_ARCH_FEAT_SM103_ALL)
    // =================== tcgen05 cta_group::2 path ===========================
    const int m0 = mp0 + rank * 128;           // this CTA's 128 A rows
    const int nb0 = n0 + rank * 128;           // this CTA's 128 B rows (N-half)

    if (wid == 0) TC_ALLOC_CG2(sbase + 0, 256);
    if (tid == 0) {
        #pragma unroll
        for (int s = 0; s < STAGES; s++) {
            MBAR_INIT(sbase + 16 + 8 * s, 2);  // ready: arrivals from both ranks
            MBAR_INIT(sbase + 80 + 8 * s, 1);  // done: one multicast commit
        }
    }
    __syncthreads();
    // all mbarriers initialized in both CTAs before any remote arrive/commit
    CLUSTER_ARRIVE();
    CLUSTER_WAIT();

    uint32_t tmem;
    asm volatile("ld.shared.b32 %0, [%1];" : "=r"(tmem) : "r"(sbase + 0));

    // idesc: F32 accum, fp16 a/b (=0), N=256, M=256 (cg2)
    const uint32_t idesc = (1u << 4) | ((TILE_N / 8) << 17) | ((TILE_M / 16) << 24);
    const uint64_t desc_base = (uint64_t(2) << 61) | (uint64_t(1) << 46)
                             | (uint64_t(64) << 32) | (uint64_t(1) << 16);

    auto load_chunk = [&](int chunk, int buf) {
        const uint32_t a_s = sbase + 1024 + buf * STAGE_BYTES;
        const uint32_t b_s = a_s + A_BYTES;
        const size_t k0 = (size_t)chunk * KC;
        #pragma unroll
        for (int j = 0; j < 4; j++) {               // A: 128 rows x 8 x 16B
            int idx = tid + GTHREADS * j;
            int row = idx >> 3, kb = (idx & 7) * 16;
            cp16(a_s + SWZ(row * 128 + kb),
                 g_xh + (size_t)(m0 + row) * KK + k0 + (kb >> 1));
        }
        #pragma unroll
        for (int j = 0; j < 4; j++) {               // B half: 128 rows x 8 x 16B
            int idx = tid + GTHREADS * j;
            int row = idx >> 3, kb = (idx & 7) * 16;
            cp16(b_s + SWZ(row * 128 + kb),
                 g_wh + (size_t)(nb0 + row) * KK + k0 + (kb >> 1));
        }
        asm volatile("cp.async.commit_group;" ::: "memory");
    };

    #pragma unroll
    for (int s = 0; s < LEAD; s++) load_chunk(s, s);

    for (int i = 0; i < NCHUNK; i++) {
        const int buf = i - (i / STAGES) * STAGES;   // i % 6
        // retire chunk i's cp group: pending = min(LEAD, NCHUNK - i) groups
        if (i < NCHUNK - 3)      { asm volatile("cp.async.wait_group 3;" ::: "memory"); }
        else if (i == NCHUNK - 3){ asm volatile("cp.async.wait_group 2;" ::: "memory"); }
        else if (i == NCHUNK - 2){ asm volatile("cp.async.wait_group 1;" ::: "memory"); }
        else                     { asm volatile("cp.async.wait_group 0;" ::: "memory"); }
        __syncthreads();
        FENCE_ASYNC();
        if (tid == 0) MBAR_ARRIVE_RANK0(sbase + 16 + 8 * buf);   // stage filled (this rank)

        if (rank == 0 && tid == 0) {
            MBAR_WAIT_CLU(sbase + 16 + 8 * buf, (i / STAGES) & 1);  // both ranks filled
            const uint32_t a_s = sbase + 1024 + buf * STAGE_BYTES;
            uint64_t ad = desc_base | ((a_s >> 4) & 0x3FFF);
            uint64_t bd = desc_base | (((a_s + A_BYTES) >> 4) & 0x3FFF);
            #pragma unroll
            for (int ks = 0; ks < 4; ks++)
                asm volatile(
                    "{\n\t.reg .pred p;\n\tsetp.ne.u32 p, %5, 0;\n\t"
                    "tcgen05.mma.cta_group::2.kind::f16 [%0], %1, %2, %3, "
                    "{%4, %4, %4, %4, %4, %4, %4, %4}, p;\n\t}"
                    :: "r"(tmem), "l"(ad + ks * 2), "l"(bd + ks * 2), "r"(idesc),
                       "r"(0u), "r"((i == 0 && ks == 0) ? 0u : 1u) : "memory");
            TC_COMMIT_MC2(sbase + 80 + 8 * buf);   // done -> both ranks
        }

        // load chunk c = i+LEAD; its buffer was used by chunk c-STAGES
        const int c = i + LEAD;
        if (c < NCHUNK) {
            const int cb = c - (c / STAGES) * STAGES;
            if (c >= STAGES)
                MBAR_WAIT(sbase + 80 + 8 * cb, ((c - STAGES) / STAGES) & 1);
            load_chunk(c, cb);
        }
    }

    // all MMAs complete (in-order): wait last chunk's done
    MBAR_WAIT(sbase + 80 + 8 * ((NCHUNK - 1) % STAGES),
              ((NCHUNK - 1) / STAGES) & 1);
    TC_FENCE_AFTER();

    // ---- epilogue: each rank reads its 128 lanes x 256 cols fp32 ----
    if (wid < 4) {
        const float scl = __ldg(scale);
        const int m = m0 + wid * 32 + lane;
        #pragma unroll
        for (int base = 0; base < TILE_N; base += 32) {
            uint32_t r[32];
            LDTM_X32(r, tmem + base);
            TC_WAIT_LD();
            float4* op = reinterpret_cast<float4*>(out + (size_t)m * NN + n0 + base);
            #pragma unroll
            for (int c2 = 0; c2 < 32; c2 += 4) {
                float4 v;
                v.x = __uint_as_float(r[c2 + 0]) * scl + __ldg(&bias[n0 + base + c2 + 0]);
                v.y = __uint_as_float(r[c2 + 1]) * scl + __ldg(&bias[n0 + base + c2 + 1]);
                v.z = __uint_as_float(r[c2 + 2]) * scl + __ldg(&bias[n0 + base + c2 + 2]);
                v.w = __uint_as_float(r[c2 + 3]) * scl + __ldg(&bias[n0 + base + c2 + 3]);
                op[c2 >> 2] = v;
            }
        }
        TC_FENCE_BEFORE();
    }
    __syncthreads();
    if (wid == 0) {
        TC_RELINQ_CG2();
        TC_DEALLOC_CG2(tmem, 256);
    }
    // no CTA may exit while peer-reading MMA/commit traffic could be in flight
    CLUSTER_ARRIVE();
    CLUSTER_WAIT();

#else
    // =================== HMMA fallback (128x256 per CTA) =====================
    const int m0 = mp0 + rank * 128;
    const int wm = (wid >> 2) * WARP_M;
    const int wn = (wid & 3) * WARP_N;

    auto load_chunk = [&](int chunk, int buf) {
        const uint32_t a_s = sbase + buf * HM_STAGE;
        const uint32_t b_s = a_s + HM_A_BYTES;
        const size_t k0 = (size_t)chunk * KC;
        #pragma unroll
        for (int j = 0; j < 4; j++) {
            int idx = tid + GTHREADS * j;
            int row = idx >> 3, kb = (idx & 7) * 16;
            cp16(a_s + SWZ(row * 128 + kb),
                 g_xh + (size_t)(m0 + row) * KK + k0 + (kb >> 1));
        }
        #pragma unroll
        for (int j = 0; j < 8; j++) {
            int idx = tid + GTHREADS * j;
            int row = idx >> 3, kb = (idx & 7) * 16;
            cp16(b_s + SWZ(row * 128 + kb),
                 g_wh + (size_t)(n0 + row) * KK + k0 + (kb >> 1));
        }
        asm volatile("cp.async.commit_group;" ::: "memory");
    };

    float acc[MT][NT][4];
    #pragma unroll
    for (int i = 0; i < MT; i++)
        #pragma unroll
        for (int j = 0; j < NT; j++)
            #pragma unroll
            for (int c = 0; c < 4; c++) acc[i][j][c] = 0.f;

    #pragma unroll
    for (int s = 0; s < 3; s++) load_chunk(s, s);

    const int a_row = wm + (lane & 15);
    const int a_kb  = (lane >> 4) * 16;
    const int b_row = wn + ((lane >> 4) << 3) + (lane & 7);
    const int b_kb  = ((lane >> 3) & 1) * 16;

    for (int i = 0; i < NCHUNK; i++) {
        const int buf = i & 3;
        if (i < NCHUNK - 3) { asm volatile("cp.async.wait_group 2;" ::: "memory"); }
        else                { asm volatile("cp.async.wait_group 0;" ::: "memory"); }
        __syncthreads();

        const uint32_t a_s = sbase + buf * HM_STAGE;
        const uint32_t b_s = a_s + HM_A_BYTES;

        #pragma unroll
        for (int ks = 0; ks < 4; ks++) {
            uint32_t af[MT][4], bf[4][4];
            #pragma unroll
            for (int mt = 0; mt < MT; mt++)
                ldsm_x4(af[mt], a_s + SWZ((a_row + mt * 16) * 128 + ks * 32 + a_kb));
            #pragma unroll
            for (int j = 0; j < 4; j++)
                ldsm_x4(bf[j], b_s + SWZ((b_row + j * 16) * 128 + ks * 32 + b_kb));
            #pragma unroll
            for (int mt = 0; mt < MT; mt++)
                #pragma unroll
                for (int nt = 0; nt < NT; nt++)
                    mma16816(acc[mt][nt], af[mt], bf[nt >> 1] + (nt & 1) * 2);
        }

        if (i + 3 < NCHUNK) load_chunk(i + 3, (i + 3) & 3);
    }

    const float scl = __ldg(scale);
    const int gid = lane >> 2, tq = lane & 3;
    #pragma unroll
    for (int mt = 0; mt < MT; mt++) {
        const size_t r0 = (size_t)(m0 + wm + mt * 16 + gid) * NN;
        const size_t r1 = r0 + 8 * NN;
        #pragma unroll
        for (int nt = 0; nt < NT; nt++) {
            const int col = n0 + wn + nt * 8 + tq * 2;
            const float2 bv = *reinterpret_cast<const float2*>(bias + col);
            float2 v0, v1;
            v0.x = acc[mt][nt][0] * scl + bv.x;
            v0.y = acc[mt][nt][1] * scl + bv.y;
            v1.x = acc[mt][nt][2] * scl + bv.x;
            v1.y = acc[mt][nt][3] * scl + bv.y;
            *reinterpret_cast<float2*>(out + r0 + col) = v0;
            *reinterpret_cast<float2*>(out + r1 + col) = v1;
        }
    }
#endif
}

// ---------------- launch -----------------------------------------------------
extern "C" void kernel_launch(void* const* d_in, const int* in_sizes, int n_in,
                              void* d_out, int out_size) {
    const float* x     = (const float*)d_in[0];
    const int*   wq    = (const int*)d_in[1];
    const float* scale = (const float*)d_in[2];
    const float* bias  = (const float*)d_in[3];
    float* out = (float*)d_out;

    cvt_x_kernel<<<16777216 / 256, 256>>>(reinterpret_cast<const float4*>(x));
    cvt_w_kernel<<<4194304 / 256, 256>>>(reinterpret_cast<const int4*>(wq));

    static bool attr_set = false;
    if (!attr_set) {
        cudaFuncSetAttribute(gemm_kernel, cudaFuncAttributeMaxDynamicSharedMemorySize,
                             SMEM_TOTAL);
        attr_set = true;
    }
    // grid: x = cluster rank pair, y = n-block, z = m-pair (z slowest -> A reuse per wave)
    dim3 grid(2, NN / TILE_N, MM / TILE_M);   // (2, 16, 64)
    gemm_kernel<<<grid, GTHREADS, SMEM_TOTAL>>>(scale, bias, out);
}

// round 9
// speedup vs baseline: 1.3781x; 1.3781x over previous
#include <cuda_runtime.h>
#include <cuda_fp16.h>
#include <cstdint>
#include <cstddef>

// y[M,N] = x[M,K] @ W[N,K]^T * scale + bias   M=16384, N=4096, K=4096
// tcgen05 cg1, 256x256 tile per single CTA = two 128x256 MMAs into TMEM halves
// (cols 0-255 / 256-511). cg2 traffic benefit, zero cross-CTA sync (R6 lesson).
// x fp32->fp16 scratch, w int32->fp16 (ints <127 exact), fp32 accumulate.
// R8 was an infra failure; this is the same audited design resubmitted.

#define MM 16384
#define NN 4096
#define KK 4096

#define TILE_M 256
#define TILE_N 256
#define KC 64                  // halves per K-chunk = 128 bytes per row
#define STAGES 3
#define LEAD 2
#define NCHUNK (KK / KC)       // 64
#define GTHREADS 256

// HMMA fallback warp tiling (128x256 half-tile): 2 (M) x 4 (N) warps, each 64x64
#define WARP_M 64
#define WARP_N 64
#define MT 4
#define NT 8

__device__ __half g_xh[(size_t)MM * KK];   // 128 MB scratch
__device__ __half g_wh[(size_t)NN * KK];   // 32 MB scratch (L2 resident)

#define A_BYTES 32768                      // 256 rows x 128 B
#define B_BYTES 32768                      // 256 rows x 128 B
#define STAGE_BYTES (A_BYTES + B_BYTES)    // 64 KB
#define SMEM_TOTAL (1024 + STAGES * STAGE_BYTES)   // 197632
// header: [0] tmem ptr, done[s] mbarriers @ 16+8s

// HMMA fallback smem layout (4 stages x 48KB at offset 0)
#define HM_A_BYTES (128 * 128)
#define HM_B_BYTES (256 * 128)
#define HM_STAGE (HM_A_BYTES + HM_B_BYTES)

#define SWZ(o) ((o) ^ (((o) >> 3) & 0x70))

__device__ __forceinline__ uint32_t s2u(const void* p) {
    uint32_t a;
    asm("{ .reg .u64 t; cvta.to.shared.u64 t, %1; cvt.u32.u64 %0, t; }" : "=r"(a) : "l"(p));
    return a;
}

__device__ __forceinline__ void cp16(uint32_t dst, const void* src) {
    asm volatile("cp.async.cg.shared.global [%0], [%1], 16;" :: "r"(dst), "l"(src) : "memory");
}

// ---------------- HMMA helpers ----------------------------------------------
__device__ __forceinline__ void ldsm_x4(uint32_t* r, uint32_t addr) {
    asm volatile("ldmatrix.sync.aligned.m8n8.x4.shared.b16 {%0,%1,%2,%3}, [%4];"
                 : "=r"(r[0]), "=r"(r[1]), "=r"(r[2]), "=r"(r[3]) : "r"(addr));
}

__device__ __forceinline__ void mma16816(float* c, const uint32_t* a, const uint32_t* b) {
    asm volatile(
        "mma.sync.aligned.m16n8k16.row.col.f32.f16.f16.f32 "
        "{%0,%1,%2,%3}, {%4,%5,%6,%7}, {%8,%9}, {%0,%1,%2,%3};"
        : "+f"(c[0]), "+f"(c[1]), "+f"(c[2]), "+f"(c[3])
        : "r"(a[0]), "r"(a[1]), "r"(a[2]), "r"(a[3]), "r"(b[0]), "r"(b[1]));
}

// ---------------- mbarrier / tcgen05 helpers ---------------------------------
#define MBAR_INIT(a, c) \
    asm volatile("mbarrier.init.shared.b64 [%0], %1;" :: "r"(a), "r"(c) : "memory")

#define MBAR_WAIT(a, par) do {                                                  \
    uint32_t _m = (a), _p = (par);                                              \
    asm volatile(                                                               \
        "{\n\t.reg .pred P1;\n\t"                                               \
        "WL_%=:\n\t"                                                            \
        "mbarrier.try_wait.parity.acquire.cta.shared::cta.b64 P1, [%0], %1, 0x989680;\n\t" \
        "@P1 bra.uni WD_%=;\n\t"                                                \
        "bra.uni WL_%=;\n\t"                                                    \
        "WD_%=:\n\t}"                                                           \
        :: "r"(_m), "r"(_p) : "memory");                                        \
} while (0)

#define TC_COMMIT(a) \
    asm volatile("tcgen05.commit.cta_group::1.mbarrier::arrive::one.shared::cluster.b64 [%0];" \
                 :: "r"(a) : "memory")
#define TC_ALLOC(sa, n) \
    asm volatile("tcgen05.alloc.cta_group::1.sync.aligned.shared::cta.b32 [%0], %1;" \
                 :: "r"(sa), "r"((uint32_t)(n)) : "memory")
#define TC_DEALLOC(t, n) \
    asm volatile("tcgen05.dealloc.cta_group::1.sync.aligned.b32 %0, %1;" :: "r"(t), "r"((uint32_t)(n)))
#define TC_RELINQ() \
    asm volatile("tcgen05.relinquish_alloc_permit.cta_group::1.sync.aligned;")
#define TC_FENCE_AFTER()  asm volatile("tcgen05.fence::after_thread_sync;" ::: "memory")
#define TC_FENCE_BEFORE() asm volatile("tcgen05.fence::before_thread_sync;" ::: "memory")
#define TC_WAIT_LD()      asm volatile("tcgen05.wait::ld.sync.aligned;" ::: "memory")
#define FENCE_ASYNC()     asm volatile("fence.proxy.async.shared::cta;" ::: "memory")

#define LDTM_X32(r, ta)                                                         \
    asm volatile(                                                               \
        "tcgen05.ld.sync.aligned.32x32b.x32.b32 "                               \
        "{%0, %1, %2, %3, %4, %5, %6, %7, "                                     \
        " %8, %9, %10, %11, %12, %13, %14, %15, "                               \
        " %16, %17, %18, %19, %20, %21, %22, %23, "                             \
        " %24, %25, %26, %27, %28, %29, %30, %31}, [%32];"                      \
        : "=r"((r)[0]),  "=r"((r)[1]),  "=r"((r)[2]),  "=r"((r)[3]),            \
          "=r"((r)[4]),  "=r"((r)[5]),  "=r"((r)[6]),  "=r"((r)[7]),            \
          "=r"((r)[8]),  "=r"((r)[9]),  "=r"((r)[10]), "=r"((r)[11]),           \
          "=r"((r)[12]), "=r"((r)[13]), "=r"((r)[14]), "=r"((r)[15]),           \
          "=r"((r)[16]), "=r"((r)[17]), "=r"((r)[18]), "=r"((r)[19]),           \
          "=r"((r)[20]), "=r"((r)[21]), "=r"((r)[22]), "=r"((r)[23]),           \
          "=r"((r)[24]), "=r"((r)[25]), "=r"((r)[26]), "=r"((r)[27]),           \
          "=r"((r)[28]), "=r"((r)[29]), "=r"((r)[30]), "=r"((r)[31])            \
        : "r"(ta))

// ---------------- conversion kernels ----------------------------------------
struct h4 { __half2 a, b; };

__global__ void cvt_x_kernel(const float4* __restrict__ x) {
    size_t i = (size_t)blockIdx.x * blockDim.x + threadIdx.x;
    float4 v = x[i];
    h4 o;
    o.a = __floats2half2_rn(v.x, v.y);
    o.b = __floats2half2_rn(v.z, v.w);
    reinterpret_cast<h4*>(g_xh)[i] = o;
}

__global__ void cvt_w_kernel(const int4* __restrict__ w) {
    size_t i = (size_t)blockIdx.x * blockDim.x + threadIdx.x;
    int4 v = w[i];
    h4 o;
    o.a = __halves2half2(__int2half_rn(v.x), __int2half_rn(v.y));
    o.b = __halves2half2(__int2half_rn(v.z), __int2half_rn(v.w));
    reinterpret_cast<h4*>(g_wh)[i] = o;
}

// ---------------- GEMM -------------------------------------------------------
// grid = (NN/256, MM/256) = (16, 64); one CTA owns a 256x256 output tile
__global__ void __launch_bounds__(GTHREADS, 1)
gemm_kernel(const float* __restrict__ scale, const float* __restrict__ bias,
            float* __restrict__ out) {
    extern __shared__ char smem[];
    const uint32_t sbase = s2u(smem);
    const int tid = threadIdx.x;
    const int wid = tid >> 5, lane = tid & 31;
    const int n0 = blockIdx.x * TILE_N;
    const int m0 = blockIdx.y * TILE_M;

#if defined(__CUDA_ARCH__) && defined(__CUDA_ARCH_FEAT_SM103_ALL)
    // =================== tcgen05 path: two 128x256 MMAs per chunk ============
    if (wid == 0) TC_ALLOC(sbase + 0, 512);
    if (tid == 0) {
        #pragma unroll
        for (int s = 0; s < STAGES; s++) MBAR_INIT(sbase + 16 + 8 * s, 1);
    }
    __syncthreads();
    uint32_t tmem;
    asm volatile("ld.shared.b32 %0, [%1];" : "=r"(tmem) : "r"(sbase + 0));

    // idesc: F32 accum, fp16 a/b, M=128 per MMA, N=256
    const uint32_t idesc = (1u << 4) | ((TILE_N / 8) << 17) | (8u << 24);
    const uint64_t desc_base = (uint64_t(2) << 61) | (uint64_t(1) << 46)
                             | (uint64_t(64) << 32) | (uint64_t(1) << 16);

    auto load_chunk = [&](int chunk, int buf) {
        const uint32_t a_s = sbase + 1024 + buf * STAGE_BYTES;
        const uint32_t b_s = a_s + A_BYTES;
        const size_t k0 = (size_t)chunk * KC;
        #pragma unroll
        for (int j = 0; j < 8; j++) {               // A: 256 rows x 8 x 16B
            int idx = tid + GTHREADS * j;
            int row = idx >> 3, kb = (idx & 7) * 16;
            cp16(a_s + SWZ(row * 128 + kb),
                 g_xh + (size_t)(m0 + row) * KK + k0 + (kb >> 1));
        }
        #pragma unroll
        for (int j = 0; j < 8; j++) {               // B: 256 rows x 8 x 16B
            int idx = tid + GTHREADS * j;
            int row = idx >> 3, kb = (idx & 7) * 16;
            cp16(b_s + SWZ(row * 128 + kb),
                 g_wh + (size_t)(n0 + row) * KK + k0 + (kb >> 1));
        }
        asm volatile("cp.async.commit_group;" ::: "memory");
    };

    load_chunk(0, 0);
    load_chunk(1, 1);

    for (int i = 0; i < NCHUNK; i++) {
        const int buf = i - (i / STAGES) * STAGES;      // i % 3
        // retire chunk i's group: 2 pending while i+1 issued, else only i
        if (i < NCHUNK - 1) { asm volatile("cp.async.wait_group 1;" ::: "memory"); }
        else                { asm volatile("cp.async.wait_group 0;" ::: "memory"); }
        __syncthreads();
        FENCE_ASYNC();
        if (tid == 0) {
            const uint32_t a_s = sbase + 1024 + buf * STAGE_BYTES;
            const uint64_t ad0 = desc_base | ((a_s >> 4) & 0x3FFF);
            const uint64_t ad1 = desc_base | (((a_s + 16384) >> 4) & 0x3FFF);
            const uint64_t bd  = desc_base | (((a_s + A_BYTES) >> 4) & 0x3FFF);
            #pragma unroll
            for (int ks = 0; ks < 4; ks++) {
                const uint32_t acc = (i == 0 && ks == 0) ? 0u : 1u;
                asm volatile(
                    "{\n\t.reg .pred p;\n\tsetp.ne.u32 p, %5, 0;\n\t"
                    "tcgen05.mma.cta_group::1.kind::f16 [%0], %1, %2, %3, {%4, %4, %4, %4}, p;\n\t}"
                    :: "r"(tmem), "l"(ad0 + ks * 2), "l"(bd + ks * 2), "r"(idesc),
                       "r"(0u), "r"(acc) : "memory");
                asm volatile(
                    "{\n\t.reg .pred p;\n\tsetp.ne.u32 p, %5, 0;\n\t"
                    "tcgen05.mma.cta_group::1.kind::f16 [%0], %1, %2, %3, {%4, %4, %4, %4}, p;\n\t}"
                    :: "r"(tmem + 256), "l"(ad1 + ks * 2), "l"(bd + ks * 2), "r"(idesc),
                       "r"(0u), "r"(acc) : "memory");
            }
            TC_COMMIT(sbase + 16 + 8 * buf);
        }
        // load chunk c = i+2 into buf c%3; previous user c-3 must be MMA-done
        const int c = i + LEAD;
        if (c < NCHUNK) {
            const int cb = c - (c / STAGES) * STAGES;
            if (c >= STAGES)
                MBAR_WAIT(sbase + 16 + 8 * cb, (((c - STAGES) / STAGES) & 1));
            load_chunk(c, cb);
        }
    }

    MBAR_WAIT(sbase + 16 + 8 * ((NCHUNK - 1) % STAGES),
              ((NCHUNK - 1) / STAGES) & 1);
    TC_FENCE_AFTER();

    // ---- epilogue: 8 warps; wid>>2 selects M-half (TMEM col half) ----
    {
        const float scl = __ldg(scale);
        const int half = wid >> 2;
        const int m = m0 + half * 128 + (wid & 3) * 32 + lane;
        const uint32_t dbase = tmem + half * 256;
        #pragma unroll
        for (int base = 0; base < TILE_N; base += 32) {
            uint32_t r[32];
            LDTM_X32(r, dbase + base);
            TC_WAIT_LD();
            float4* op = reinterpret_cast<float4*>(out + (size_t)m * NN + n0 + base);
            #pragma unroll
            for (int c2 = 0; c2 < 32; c2 += 4) {
                float4 v;
                v.x = __uint_as_float(r[c2 + 0]) * scl + __ldg(&bias[n0 + base + c2 + 0]);
                v.y = __uint_as_float(r[c2 + 1]) * scl + __ldg(&bias[n0 + base + c2 + 1]);
                v.z = __uint_as_float(r[c2 + 2]) * scl + __ldg(&bias[n0 + base + c2 + 2]);
                v.w = __uint_as_float(r[c2 + 3]) * scl + __ldg(&bias[n0 + base + c2 + 3]);
                op[c2 >> 2] = v;
            }
        }
        TC_FENCE_BEFORE();
    }
    __syncthreads();
    if (wid == 0) {
        TC_RELINQ();
        TC_DEALLOC(tmem, 512);
    }

#else
    // =================== HMMA fallback: two sequential 128x256 passes ========
    const int wm = (wid >> 2) * WARP_M;
    const int wn = (wid & 3) * WARP_N;

    for (int half = 0; half < 2; half++) {
        const int m0h = m0 + half * 128;

        auto load_chunk = [&](int chunk, int buf) {
            const uint32_t a_s = sbase + buf * HM_STAGE;
            const uint32_t b_s = a_s + HM_A_BYTES;
            const size_t k0 = (size_t)chunk * KC;
            #pragma unroll
            for (int j = 0; j < 4; j++) {
                int idx = tid + GTHREADS * j;
                int row = idx >> 3, kb = (idx & 7) * 16;
                cp16(a_s + SWZ(row * 128 + kb),
                     g_xh + (size_t)(m0h + row) * KK + k0 + (kb >> 1));
            }
            #pragma unroll
            for (int j = 0; j < 8; j++) {
                int idx = tid + GTHREADS * j;
                int row = idx >> 3, kb = (idx & 7) * 16;
                cp16(b_s + SWZ(row * 128 + kb),
                     g_wh + (size_t)(n0 + row) * KK + k0 + (kb >> 1));
            }
            asm volatile("cp.async.commit_group;" ::: "memory");
        };

        float acc[MT][NT][4];
        #pragma unroll
        for (int i = 0; i < MT; i++)
            #pragma unroll
            for (int j = 0; j < NT; j++)
                #pragma unroll
                for (int c = 0; c < 4; c++) acc[i][j][c] = 0.f;

        #pragma unroll
        for (int s = 0; s < 3; s++) load_chunk(s, s);

        const int a_row = wm + (lane & 15);
        const int a_kb  = (lane >> 4) * 16;
        const int b_row = wn + ((lane >> 4) << 3) + (lane & 7);
        const int b_kb  = ((lane >> 3) & 1) * 16;

        for (int i = 0; i < NCHUNK; i++) {
            const int buf = i & 3;
            if (i < NCHUNK - 3) { asm volatile("cp.async.wait_group 2;" ::: "memory"); }
            else                { asm volatile("cp.async.wait_group 0;" ::: "memory"); }
            __syncthreads();

            const uint32_t a_s = sbase + buf * HM_STAGE;
            const uint32_t b_s = a_s + HM_A_BYTES;

            #pragma unroll
            for (int ks = 0; ks < 4; ks++) {
                uint32_t af[MT][4], bf[4][4];
                #pragma unroll
                for (int mt = 0; mt < MT; mt++)
                    ldsm_x4(af[mt], a_s + SWZ((a_row + mt * 16) * 128 + ks * 32 + a_kb));
                #pragma unroll
                for (int j = 0; j < 4; j++)
                    ldsm_x4(bf[j], b_s + SWZ((b_row + j * 16) * 128 + ks * 32 + b_kb));
                #pragma unroll
                for (int mt = 0; mt < MT; mt++)
                    #pragma unroll
                    for (int nt = 0; nt < NT; nt++)
                        mma16816(acc[mt][nt], af[mt], bf[nt >> 1] + (nt & 1) * 2);
            }

            if (i + 3 < NCHUNK) load_chunk(i + 3, (i + 3) & 3);
        }

        const float scl = __ldg(scale);
        const int gid = lane >> 2, tq = lane & 3;
        #pragma unroll
        for (int mt = 0; mt < MT; mt++) {
            const size_t r0 = (size_t)(m0h + wm + mt * 16 + gid) * NN;
            const size_t r1 = r0 + 8 * NN;
            #pragma unroll
            for (int nt = 0; nt < NT; nt++) {
                const int col = n0 + wn + nt * 8 + tq * 2;
                const float2 bv = *reinterpret_cast<const float2*>(bias + col);
                float2 v0, v1;
                v0.x = acc[mt][nt][0] * scl + bv.x;
                v0.y = acc[mt][nt][1] * scl + bv.y;
                v1.x = acc[mt][nt][2] * scl + bv.x;
                v1.y = acc[mt][nt][3] * scl + bv.y;
                *reinterpret_cast<float2*>(out + r0 + col) = v0;
                *reinterpret_cast<float2*>(out + r1 + col) = v1;
            }
        }
        __syncthreads();   // drain before buffer reuse in second pass
    }
#endif
}

// ---------------- launch -----------------------------------------------------
extern "C" void kernel_launch(void* const* d_in, const int* in_sizes, int n_in,
                              void* d_out, int out_size) {
    const float* x     = (const float*)d_in[0];
    const int*   wq    = (const int*)d_in[1];
    const float* scale = (const float*)d_in[2];
    const float* bias  = (const float*)d_in[3];
    float* out = (float*)d_out;

    cvt_x_kernel<<<16777216 / 256, 256>>>(reinterpret_cast<const float4*>(x));
    cvt_w_kernel<<<4194304 / 256, 256>>>(reinterpret_cast<const int4*>(wq));

    static bool attr_set = false;
    if (!attr_set) {
        cudaFuncSetAttribute(gemm_kernel, cudaFuncAttributeMaxDynamicSharedMemorySize,
                             SMEM_TOTAL);
        attr_set = true;
    }
    dim3 grid(NN / TILE_N, MM / TILE_M);   // (16, 64): N fastest -> W stays L2-hot
    gemm_kernel<<<grid, GTHREADS, SMEM_TOTAL>>>(scale, bias, out);
}

// round 12
// speedup vs baseline: 1.4353x; 1.0416x over previous
#include <cuda_runtime.h>
#include <cuda_fp16.h>
#include <cstdint>
#include <cstddef>

// y[M,N] = x[M,K] @ W[N,K]^T * scale + bias   M=16384, N=4096, K=4096
// tcgen05 cg1, 256x256 tile/CTA (two 128x256 MMAs into TMEM halves), now as a
// PERSISTENT kernel: atomic tile scheduler + cross-tile pipelining (next tile's
// chunks 0,1 loaded under previous tile's tail + epilogue). Global chunk index
// g is consecutive per CTA -> buffer = g%3, wait parity = (g/3-1)&1 stay exact.
// x fp32->fp16 scratch, w int32->fp16 (ints <127 exact), fp32 accumulate.

#define MM 16384
#define NN 4096
#define KK 4096

#define TILE_M 256
#define TILE_N 256
#define KC 64                  // halves per K-chunk = 128 bytes per row
#define STAGES 3
#define NCHUNK (KK / KC)       // 64
#define GTHREADS 256
#define NTILES ((MM / TILE_M) * (NN / TILE_N))   // 1024
#define GRID_P 152             // GB300 SM count

// HMMA fallback warp tiling (128x256 half-tile): 2 (M) x 4 (N) warps, each 64x64
#define WARP_M 64
#define WARP_N 64
#define MT 4
#define NT 8

__device__ __half g_xh[(size_t)MM * KK];   // 128 MB scratch
__device__ __half g_wh[(size_t)NN * KK];   // 32 MB scratch (L2 resident)
__device__ int g_ctr;                      // persistent tile counter

#define A_BYTES 32768                      // 256 rows x 128 B
#define B_BYTES 32768                      // 256 rows x 128 B
#define STAGE_BYTES (A_BYTES + B_BYTES)    // 64 KB
#define SMEM_TOTAL (1024 + STAGES * STAGE_BYTES)   // 197632
// header: [0] tmem ptr, [8] t_next slot, done[s] mbarriers @ 16+8s

// HMMA fallback smem layout (4 stages x 48KB at offset 0; t slot at 196608)
#define HM_A_BYTES (128 * 128)
#define HM_B_BYTES (256 * 128)
#define HM_STAGE (HM_A_BYTES + HM_B_BYTES)

#define SWZ(o) ((o) ^ (((o) >> 3) & 0x70))

__device__ __forceinline__ uint32_t s2u(const void* p) {
    uint32_t a;
    asm("{ .reg .u64 t; cvta.to.shared.u64 t, %1; cvt.u32.u64 %0, t; }" : "=r"(a) : "l"(p));
    return a;
}

__device__ __forceinline__ void cp16(uint32_t dst, const void* src) {
    asm volatile("cp.async.cg.shared.global [%0], [%1], 16;" :: "r"(dst), "l"(src) : "memory");
}

// ---------------- HMMA helpers ----------------------------------------------
__device__ __forceinline__ void ldsm_x4(uint32_t* r, uint32_t addr) {
    asm volatile("ldmatrix.sync.aligned.m8n8.x4.shared.b16 {%0,%1,%2,%3}, [%4];"
                 : "=r"(r[0]), "=r"(r[1]), "=r"(r[2]), "=r"(r[3]) : "r"(addr));
}

__device__ __forceinline__ void mma16816(float* c, const uint32_t* a, const uint32_t* b) {
    asm volatile(
        "mma.sync.aligned.m16n8k16.row.col.f32.f16.f16.f32 "
        "{%0,%1,%2,%3}, {%4,%5,%6,%7}, {%8,%9}, {%0,%1,%2,%3};"
        : "+f"(c[0]), "+f"(c[1]), "+f"(c[2]), "+f"(c[3])
        : "r"(a[0]), "r"(a[1]), "r"(a[2]), "r"(a[3]), "r"(b[0]), "r"(b[1]));
}

// ---------------- mbarrier / tcgen05 helpers ---------------------------------
#define MBAR_INIT(a, c) \
    asm volatile("mbarrier.init.shared.b64 [%0], %1;" :: "r"(a), "r"(c) : "memory")

#define MBAR_WAIT(a, par) do {                                                  \
    uint32_t _m = (a), _p = (par);                                              \
    asm volatile(                                                               \
        "{\n\t.reg .pred P1;\n\t"                                               \
        "WL_%=:\n\t"                                                            \
        "mbarrier.try_wait.parity.acquire.cta.shared::cta.b64 P1, [%0], %1, 0x989680;\n\t" \
        "@P1 bra.uni WD_%=;\n\t"                                                \
        "bra.uni WL_%=;\n\t"                                                    \
        "WD_%=:\n\t}"                                                           \
        :: "r"(_m), "r"(_p) : "memory");                                        \
} while (0)

#define TC_COMMIT(a) \
    asm volatile("tcgen05.commit.cta_group::1.mbarrier::arrive::one.shared::cluster.b64 [%0];" \
                 :: "r"(a) : "memory")
#define TC_ALLOC(sa, n) \
    asm volatile("tcgen05.alloc.cta_group::1.sync.aligned.shared::cta.b32 [%0], %1;" \
                 :: "r"(sa), "r"((uint32_t)(n)) : "memory")
#define TC_DEALLOC(t, n) \
    asm volatile("tcgen05.dealloc.cta_group::1.sync.aligned.b32 %0, %1;" :: "r"(t), "r"((uint32_t)(n)))
#define TC_RELINQ() \
    asm volatile("tcgen05.relinquish_alloc_permit.cta_group::1.sync.aligned;")
#define TC_FENCE_AFTER()  asm volatile("tcgen05.fence::after_thread_sync;" ::: "memory")
#define TC_FENCE_BEFORE() asm volatile("tcgen05.fence::before_thread_sync;" ::: "memory")
#define TC_WAIT_LD()      asm volatile("tcgen05.wait::ld.sync.aligned;" ::: "memory")
#define FENCE_ASYNC()     asm volatile("fence.proxy.async.shared::cta;" ::: "memory")

#define LDTM_X32(r, ta)                                                         \
    asm volatile(                                                               \
        "tcgen05.ld.sync.aligned.32x32b.x32.b32 "                               \
        "{%0, %1, %2, %3, %4, %5, %6, %7, "                                     \
        " %8, %9, %10, %11, %12, %13, %14, %15, "                               \
        " %16, %17, %18, %19, %20, %21, %22, %23, "                             \
        " %24, %25, %26, %27, %28, %29, %30, %31}, [%32];"                      \
        : "=r"((r)[0]),  "=r"((r)[1]),  "=r"((r)[2]),  "=r"((r)[3]),            \
          "=r"((r)[4]),  "=r"((r)[5]),  "=r"((r)[6]),  "=r"((r)[7]),            \
          "=r"((r)[8]),  "=r"((r)[9]),  "=r"((r)[10]), "=r"((r)[11]),           \
          "=r"((r)[12]), "=r"((r)[13]), "=r"((r)[14]), "=r"((r)[15]),           \
          "=r"((r)[16]), "=r"((r)[17]), "=r"((r)[18]), "=r"((r)[19]),           \
          "=r"((r)[20]), "=r"((r)[21]), "=r"((r)[22]), "=r"((r)[23]),           \
          "=r"((r)[24]), "=r"((r)[25]), "=r"((r)[26]), "=r"((r)[27]),           \
          "=r"((r)[28]), "=r"((r)[29]), "=r"((r)[30]), "=r"((r)[31])            \
        : "r"(ta))

// ---------------- conversion kernels ----------------------------------------
struct h4 { __half2 a, b; };

__global__ void cvt_x_kernel(const float4* __restrict__ x) {
    size_t i = (size_t)blockIdx.x * blockDim.x + threadIdx.x;
    float4 v = x[i];
    h4 o;
    o.a = __floats2half2_rn(v.x, v.y);
    o.b = __floats2half2_rn(v.z, v.w);
    reinterpret_cast<h4*>(g_xh)[i] = o;
}

__global__ void cvt_w_kernel(const int4* __restrict__ w) {
    size_t i = (size_t)blockIdx.x * blockDim.x + threadIdx.x;
    if (i == 0) g_ctr = 0;                 // reset persistent tile counter
    int4 v = w[i];
    h4 o;
    o.a = __halves2half2(__int2half_rn(v.x), __int2half_rn(v.y));
    o.b = __halves2half2(__int2half_rn(v.z), __int2half_rn(v.w));
    reinterpret_cast<h4*>(g_wh)[i] = o;
}

// ---------------- GEMM (persistent, grid = GRID_P) ---------------------------
__global__ void __launch_bounds__(GTHREADS, 1)
gemm_kernel(const float* __restrict__ scale, const float* __restrict__ bias,
            float* __restrict__ out) {
    extern __shared__ char smem[];
    const uint32_t sbase = s2u(smem);
    const int tid = threadIdx.x;
    const int wid = tid >> 5, lane = tid & 31;

#if defined(__CUDA_ARCH__) && defined(__CUDA_ARCH_FEAT_SM103_ALL)
    // =================== tcgen05 persistent path =============================
    volatile int* tslot = (volatile int*)(smem + 8);

    if (wid == 0) TC_ALLOC(sbase + 0, 512);
    if (tid == 0) {
        #pragma unroll
        for (int s = 0; s < STAGES; s++) MBAR_INIT(sbase + 16 + 8 * s, 1);
    }
    __syncthreads();
    uint32_t tmem;
    asm volatile("ld.shared.b32 %0, [%1];" : "=r"(tmem) : "r"(sbase + 0));

    const uint32_t idesc = (1u << 4) | ((TILE_N / 8) << 17) | (8u << 24);
    const uint64_t desc_base = (uint64_t(2) << 61) | (uint64_t(1) << 46)
                             | (uint64_t(64) << 32) | (uint64_t(1) << 16);
    const float scl = __ldg(scale);

    // load global chunk g for tile at (m0_, n0_); buffer/parity from g alone
    auto load_chunk = [&](int g, int m0_, int n0_) {
        const int b = g - (g / 3) * 3;
        if (g >= STAGES)
            MBAR_WAIT(sbase + 16 + 8 * b, ((g / 3 - 1) & 1));
        const uint32_t a_s = sbase + 1024 + b * STAGE_BYTES;
        const uint32_t b_s = a_s + A_BYTES;
        const size_t k0 = (size_t)(g & (NCHUNK - 1)) * KC;
        #pragma unroll
        for (int j = 0; j < 8; j++) {               // A: 256 rows x 8 x 16B
            int idx = tid + GTHREADS * j;
            int row = idx >> 3, kb = (idx & 7) * 16;
            cp16(a_s + SWZ(row * 128 + kb),
                 g_xh + (size_t)(m0_ + row) * KK + k0 + (kb >> 1));
        }
        #pragma unroll
        for (int j = 0; j < 8; j++) {               // B: 256 rows x 8 x 16B
            int idx = tid + GTHREADS * j;
            int row = idx >> 3, kb = (idx & 7) * 16;
            cp16(b_s + SWZ(row * 128 + kb),
                 g_wh + (size_t)(n0_ + row) * KK + k0 + (kb >> 1));
        }
        asm volatile("cp.async.commit_group;" ::: "memory");
    };

    if (tid == 0) tslot[0] = atomicAdd(&g_ctr, 1);
    __syncthreads();
    int t = tslot[0];
    int base = 0;

    while (t < NTILES) {
        const int n0 = (t & 15) * TILE_N;
        const int m0 = (t >> 4) * TILE_M;
        TC_FENCE_AFTER();                  // order prior epilogue LDTM vs new MMAs

        if (base == 0) {                   // very first tile: explicit prologue
            load_chunk(0, m0, n0);
            load_chunk(1, m0, n0);
        }

        for (int i = 0; i < NCHUNK; i++) {
            const int g = base + i;
            const int buf = g - (g / 3) * 3;
            // cp ledger: pending = {chunk i, +1 newer} except final tail
            if (i == NCHUNK - 1 && tslot[0] >= NTILES) {
                asm volatile("cp.async.wait_group 0;" ::: "memory");
            } else {
                asm volatile("cp.async.wait_group 1;" ::: "memory");
            }
            __syncthreads();
            FENCE_ASYNC();
            if (tid == 0) {
                if (i == 0) tslot[0] = atomicAdd(&g_ctr, 1);   // prefetch next tile
                const uint32_t a_s = sbase + 1024 + buf * STAGE_BYTES;
                const uint64_t ad0 = desc_base | ((a_s >> 4) & 0x3FFF);
                const uint64_t ad1 = desc_base | (((a_s + 16384) >> 4) & 0x3FFF);
                const uint64_t bd  = desc_base | (((a_s + A_BYTES) >> 4) & 0x3FFF);
                #pragma unroll
                for (int ks = 0; ks < 4; ks++) {
                    const uint32_t acc = (i == 0 && ks == 0) ? 0u : 1u;
                    asm volatile(
                        "{\n\t.reg .pred p;\n\tsetp.ne.u32 p, %5, 0;\n\t"
                        "tcgen05.mma.cta_group::1.kind::f16 [%0], %1, %2, %3, {%4, %4, %4, %4}, p;\n\t}"
                        :: "r"(tmem), "l"(ad0 + ks * 2), "l"(bd + ks * 2), "r"(idesc),
                           "r"(0u), "r"(acc) : "memory");
                    asm volatile(
                        "{\n\t.reg .pred p;\n\tsetp.ne.u32 p, %5, 0;\n\t"
                        "tcgen05.mma.cta_group::1.kind::f16 [%0], %1, %2, %3, {%4, %4, %4, %4}, p;\n\t}"
                        :: "r"(tmem + 256), "l"(ad1 + ks * 2), "l"(bd + ks * 2), "r"(idesc),
                           "r"(0u), "r"(acc) : "memory");
                }
                TC_COMMIT(sbase + 16 + 8 * buf);
            }
            // load chunk c: current tile for c<64, else next tile's chunks 0,1
            const int c = i + 2;
            if (c < NCHUNK) {
                load_chunk(base + c, m0, n0);
            } else {
                const int tn = tslot[0];           // written at i==0, many syncs ago
                if (tn < NTILES)
                    load_chunk(base + c, (tn >> 4) * TILE_M, (tn & 15) * TILE_N);
            }
        }

        // ---- epilogue: wait last chunk's commit (non-consuming parity) ----
        {
            const int G = base + NCHUNK - 1;
            MBAR_WAIT(sbase + 16 + 8 * (G - (G / 3) * 3), (G / 3) & 1);
            TC_FENCE_AFTER();
            const int half = wid >> 2;
            const int m = m0 + half * 128 + (wid & 3) * 32 + lane;
            const uint32_t dbase = tmem + half * 256;
            #pragma unroll
            for (int bc = 0; bc < TILE_N; bc += 32) {
                uint32_t r[32];
                LDTM_X32(r, dbase + bc);
                TC_WAIT_LD();
                float4* op = reinterpret_cast<float4*>(out + (size_t)m * NN + n0 + bc);
                #pragma unroll
                for (int c2 = 0; c2 < 32; c2 += 4) {
                    float4 v;
                    v.x = __uint_as_float(r[c2 + 0]) * scl + __ldg(&bias[n0 + bc + c2 + 0]);
                    v.y = __uint_as_float(r[c2 + 1]) * scl + __ldg(&bias[n0 + bc + c2 + 1]);
                    v.z = __uint_as_float(r[c2 + 2]) * scl + __ldg(&bias[n0 + bc + c2 + 2]);
                    v.w = __uint_as_float(r[c2 + 3]) * scl + __ldg(&bias[n0 + bc + c2 + 3]);
                    op[c2 >> 2] = v;
                }
            }
            TC_FENCE_BEFORE();
        }
        __syncthreads();
        base += NCHUNK;
        t = tslot[0];
    }

    __syncthreads();
    if (wid == 0) {
        TC_RELINQ();
        TC_DEALLOC(tmem, 512);
    }

#else
    // =================== HMMA fallback: persistent, two half passes ==========
    volatile int* tslot = (volatile int*)(smem + 4 * HM_STAGE);
    const int wm = (wid >> 2) * WARP_M;
    const int wn = (wid & 3) * WARP_N;

    if (tid == 0) tslot[0] = atomicAdd(&g_ctr, 1);
    __syncthreads();
    int t = tslot[0];

    while (t < NTILES) {
        const int n0 = (t & 15) * TILE_N;
        const int m0 = (t >> 4) * TILE_M;

        for (int half = 0; half < 2; half++) {
            const int m0h = m0 + half * 128;

            auto load_chunk = [&](int chunk, int buf) {
                const uint32_t a_s = sbase + buf * HM_STAGE;
                const uint32_t b_s = a_s + HM_A_BYTES;
                const size_t k0 = (size_t)chunk * KC;
                #pragma unroll
                for (int j = 0; j < 4; j++) {
                    int idx = tid + GTHREADS * j;
                    int row = idx >> 3, kb = (idx & 7) * 16;
                    cp16(a_s + SWZ(row * 128 + kb),
                         g_xh + (size_t)(m0h + row) * KK + k0 + (kb >> 1));
                }
                #pragma unroll
                for (int j = 0; j < 8; j++) {
                    int idx = tid + GTHREADS * j;
                    int row = idx >> 3, kb = (idx & 7) * 16;
                    cp16(b_s + SWZ(row * 128 + kb),
                         g_wh + (size_t)(n0 + row) * KK + k0 + (kb >> 1));
                }
                asm volatile("cp.async.commit_group;" ::: "memory");
            };

            float acc[MT][NT][4];
            #pragma unroll
            for (int i = 0; i < MT; i++)
                #pragma unroll
                for (int j = 0; j < NT; j++)
                    #pragma unroll
                    for (int c = 0; c < 4; c++) acc[i][j][c] = 0.f;

            #pragma unroll
            for (int s = 0; s < 3; s++) load_chunk(s, s);

            const int a_row = wm + (lane & 15);
            const int a_kb  = (lane >> 4) * 16;
            const int b_row = wn + ((lane >> 4) << 3) + (lane & 7);
            const int b_kb  = ((lane >> 3) & 1) * 16;

            for (int i = 0; i < NCHUNK; i++) {
                const int buf = i & 3;
                if (i < NCHUNK - 3) { asm volatile("cp.async.wait_group 2;" ::: "memory"); }
                else                { asm volatile("cp.async.wait_group 0;" ::: "memory"); }
                __syncthreads();

                const uint32_t a_s = sbase + buf * HM_STAGE;
                const uint32_t b_s = a_s + HM_A_BYTES;

                #pragma unroll
                for (int ks = 0; ks < 4; ks++) {
                    uint32_t af[MT][4], bf[4][4];
                    #pragma unroll
                    for (int mt = 0; mt < MT; mt++)
                        ldsm_x4(af[mt], a_s + SWZ((a_row + mt * 16) * 128 + ks * 32 + a_kb));
                    #pragma unroll
                    for (int j = 0; j < 4; j++)
                        ldsm_x4(bf[j], b_s + SWZ((b_row + j * 16) * 128 + ks * 32 + b_kb));
                    #pragma unroll
                    for (int mt = 0; mt < MT; mt++)
                        #pragma unroll
                        for (int nt = 0; nt < NT; nt++)
                            mma16816(acc[mt][nt], af[mt], bf[nt >> 1] + (nt & 1) * 2);
                }

                if (i + 3 < NCHUNK) load_chunk(i + 3, (i + 3) & 3);
            }

            const float scl = __ldg(scale);
            const int gid = lane >> 2, tq = lane & 3;
            #pragma unroll
            for (int mt = 0; mt < MT; mt++) {
                const size_t r0 = (size_t)(m0h + wm + mt * 16 + gid) * NN;
                const size_t r1 = r0 + 8 * NN;
                #pragma unroll
                for (int nt = 0; nt < NT; nt++) {
                    const int col = n0 + wn + nt * 8 + tq * 2;
                    const float2 bv = *reinterpret_cast<const float2*>(bias + col);
                    float2 v0, v1;
                    v0.x = acc[mt][nt][0] * scl + bv.x;
                    v0.y = acc[mt][nt][1] * scl + bv.y;
                    v1.x = acc[mt][nt][2] * scl + bv.x;
                    v1.y = acc[mt][nt][3] * scl + bv.y;
                    *reinterpret_cast<float2*>(out + r0 + col) = v0;
                    *reinterpret_cast<float2*>(out + r1 + col) = v1;
                }
            }
            __syncthreads();
        }

        if (tid == 0) tslot[0] = atomicAdd(&g_ctr, 1);
        __syncthreads();
        t = tslot[0];
    }
#endif
}

// ---------------- launch -----------------------------------------------------
extern "C" void kernel_launch(void* const* d_in, const int* in_sizes, int n_in,
                              void* d_out, int out_size) {
    const float* x     = (const float*)d_in[0];
    const int*   wq    = (const int*)d_in[1];
    const float* scale = (const float*)d_in[2];
    const float* bias  = (const float*)d_in[3];
    float* out = (float*)d_out;

    cvt_x_kernel<<<16777216 / 256, 256>>>(reinterpret_cast<const float4*>(x));
    cvt_w_kernel<<<4194304 / 256, 256>>>(reinterpret_cast<const int4*>(wq));

    static bool attr_set = false;
    if (!attr_set) {
        cudaFuncSetAttribute(gemm_kernel, cudaFuncAttributeMaxDynamicSharedMemorySize,
                             SMEM_TOTAL);
        attr_set = true;
    }
    gemm_kernel<<<GRID_P, GTHREADS, SMEM_TOTAL>>>(scale, bias, out);
}